// round 15
// baseline (speedup 1.0000x reference)
#include <cuda_runtime.h>
#include <cuda_fp16.h>
#include <math.h>
#include <cstdint>

#define MTOT 8192
#define NHALF 4096
#define DDIM 128
#define BM 128
#define BN 64
#define NTILES 4160             // sum_{bi<64} (128-2*bi)
#define NPERS 444               // persistent CTAs: 3 per SM x 148
#define ROWBLOCKS (MTOT / 8)
#define LDH 136                 // smem row stride in halves (272B: ldmatrix conflict-free)
#define A_HALVES (BM * LDH)
#define B_HALVES (BN * LDH)
#define SMEM_BYTES ((A_HALVES + 2 * B_HALVES) * 2)   // 69632 B -> 3 CTAs/SM

__device__ __half g_half[MTOT * DDIM];   // fp16 copy of [src; tgt]
__device__ float  g_sq[MTOT];
__device__ float  g_v[DDIM];
__device__ float  g_S = 0.f;
__device__ float  g_c2l = 0.f;           // c*log2(e): t = exp(-c*L2) = exp2(-c2l*L2)
__device__ double g_acc = 0.0;
__device__ unsigned g_done_rows = 0u;
__device__ unsigned g_done_main = 0u;

// ---------------- helpers ----------------
__device__ __forceinline__ uint32_t smem_u32(const void* p) {
    uint32_t a;
    asm("{ .reg .u64 t; cvta.to.shared.u64 t, %1; cvt.u32.u64 %0, t; }" : "=r"(a) : "l"(p));
    return a;
}
__device__ __forceinline__ void cp16(uint32_t s, const void* g) {
    asm volatile("cp.async.cg.shared.global [%0], [%1], 16;" :: "r"(s), "l"(g));
}
__device__ __forceinline__ void cp_commit() {
    asm volatile("cp.async.commit_group;" ::: "memory");
}
__device__ __forceinline__ void cp_wait1() {
    asm volatile("cp.async.wait_group 1;" ::: "memory");
}
__device__ __forceinline__ void ldsm4(uint32_t& r0, uint32_t& r1, uint32_t& r2, uint32_t& r3,
                                      uint32_t addr) {
    asm volatile("ldmatrix.sync.aligned.m8n8.x4.shared.b16 {%0,%1,%2,%3}, [%4];"
                 : "=r"(r0), "=r"(r1), "=r"(r2), "=r"(r3) : "r"(addr));
}
__device__ __forceinline__ void mma_f16(float* d, const uint32_t* a,
                                        uint32_t b0, uint32_t b1) {
    asm volatile(
        "mma.sync.aligned.m16n8k16.row.col.f32.f16.f16.f32 "
        "{%0,%1,%2,%3}, {%4,%5,%6,%7}, {%8,%9}, {%0,%1,%2,%3};"
        : "+f"(d[0]), "+f"(d[1]), "+f"(d[2]), "+f"(d[3])
        : "r"(a[0]), "r"(a[1]), "r"(a[2]), "r"(a[3]), "r"(b0), "r"(b1));
}

// ---- prep: row norms + col sums + fp16 convert; LAST block computes bandwidth ----
__global__ void k_rows(const float* __restrict__ src, const float* __restrict__ tgt) {
    __shared__ float cs[DDIM];
    __shared__ float ss;
    __shared__ unsigned s_last;
    int warp = threadIdx.x >> 5, lane = threadIdx.x & 31;
    int row = blockIdx.x * 8 + warp;
    const float* p = (row < NHALF) ? (src + (size_t)row * DDIM)
                                   : (tgt + (size_t)(row - NHALF) * DDIM);
    float4 x = ((const float4*)p)[lane];

    union { __half2 h[2]; uint2 u; } ph;
    ph.h[0] = __floats2half2_rn(x.x, x.y);
    ph.h[1] = __floats2half2_rn(x.z, x.w);
    ((uint2*)(g_half + (size_t)row * DDIM))[lane] = ph.u;

    float s = x.x*x.x + x.y*x.y + x.z*x.z + x.w*x.w;
    if (threadIdx.x < DDIM) cs[threadIdx.x] = 0.f;
    if (threadIdx.x == 0) ss = 0.f;
    __syncthreads();
    atomicAdd(&cs[lane*4+0], x.x); atomicAdd(&cs[lane*4+1], x.y);
    atomicAdd(&cs[lane*4+2], x.z); atomicAdd(&cs[lane*4+3], x.w);
    #pragma unroll
    for (int o = 16; o; o >>= 1) s += __shfl_xor_sync(0xffffffffu, s, o);
    if (lane == 0) { g_sq[row] = s; atomicAdd(&ss, s); }
    __syncthreads();
    if (threadIdx.x < DDIM) atomicAdd(&g_v[threadIdx.x], cs[threadIdx.x]);
    if (threadIdx.x == 0)   atomicAdd(&g_S, ss);

    __threadfence();
    if (threadIdx.x == 0) s_last = (atomicAdd(&g_done_rows, 1u) == ROWBLOCKS - 1);
    __syncthreads();
    if (s_last && warp == 0) {
        float vv = 0.f;
        #pragma unroll
        for (int i = 0; i < 4; i++) {
            float v = g_v[lane + 32 * i];
            vv += v * v;
        }
        #pragma unroll
        for (int o = 16; o; o >>= 1) vv += __shfl_xor_sync(0xffffffffu, vv, o);
        if (lane == 0) {
            double sumL2 = 2.0 * (double)MTOT * (double)g_S - 2.0 * (double)vv;
            double bw = sumL2 / ((double)MTOT * (double)MTOT - (double)MTOT);
            bw *= 0.25;
            double c = 1.0 / (16.0 * bw);
            g_c2l = (float)(c * 1.4426950408889634);
            g_done_rows = 0u;
        }
    }
}

// ------------ main: persistent pipelined fp16 mma kernel, 3 CTAs/SM ------------
extern __shared__ __half dsmh[];

__global__ void __launch_bounds__(256, 3)
k_main(float* __restrict__ out) {
    __half* As = dsmh;                          // A panel: 128 rows
    __half* Bs0 = dsmh + A_HALVES;              // B double buffer: 64 rows each
    __shared__ float sqA[BM];
    __shared__ float nBb[2][BN];
    __shared__ float red[8];

    int tid = threadIdx.x;
    int wid = tid >> 5, lane = tid & 31;

    int c = blockIdx.x;
    int start = (int)(((long long)c * NTILES) / NPERS);
    int end   = (int)(((long long)(c + 1) * NTILES) / NPERS);

    // decode start -> (bi, bj): C(bi) = bi*(129-bi) tiles before row bi; bj in [2bi, 128)
    int bi = (int)((129.0 - sqrt(16641.0 - 4.0 * (double)start)) * 0.5);
    while ((bi + 1) * (129 - (bi + 1)) <= start) bi++;
    while (bi * (129 - bi) > start) bi--;
    int bj = 2 * bi + (start - bi * (129 - bi));

    float c2l = g_c2l;

    uint32_t as_base = smem_u32(As);
    uint32_t bs_base = smem_u32(Bs0);

    // staging smem offsets: idx -> (row = idx>>4, q = idx&15)
    uint32_t soff[8];
    #pragma unroll
    for (int i = 0; i < 8; i++) {
        int idx = tid + i * 256;
        soff[i] = (uint32_t)((idx >> 4) * LDH + (idx & 15) * 8) * 2;
    }

    // ---- prologue: stage A(bi) [group], B(bj)->buf0 [group], sqA, nBb[0] ----
    {
        const __half* Ab = g_half + (size_t)(bi * BM) * DDIM;
        #pragma unroll
        for (int i = 0; i < 8; i++) cp16(as_base + soff[i], Ab + (tid + i * 256) * 8);
        cp_commit();
        const __half* Bb = g_half + (size_t)(bj * BN) * DDIM;
        #pragma unroll
        for (int i = 0; i < 4; i++) cp16(bs_base + soff[i], Bb + (tid + i * 256) * 8);
        cp_commit();
        if (tid < BM)            sqA[tid] = g_sq[bi * BM + tid];
        else if (tid < BM + BN)  nBb[0][tid - BM] = -c2l * g_sq[bj * BN + tid - BM];
    }

    // warp tiling: 4 (m) x 2 (n) warps; warp tile 32x32 = 2 m-atoms(16) x 4 n-atoms(8)
    int wm = wid & 3, wn = wid >> 2;
    int m0 = wm * 32, n0 = wn * 32;
    uint32_t a_addr[2], b_addr[2];
    {
        int rr = lane & 15;
        int cc = 8 * (lane >> 4);
        #pragma unroll
        for (int a = 0; a < 2; a++)
            a_addr[a] = as_base + (uint32_t)((m0 + 16 * a + rr) * LDH + cc) * 2;
        #pragma unroll
        for (int b = 0; b < 2; b++)
            b_addr[b] = bs_base + (uint32_t)((n0 + 16 * b + rr) * LDH + cc) * 2;
    }

    int g = lane >> 2, t2 = (lane & 3) * 2;
    float tc2 = 2.0f * c2l;
    float csum = 0.f;
    int buf = 0;
    bool restage = false;

    for (int t = start; t < end; t++) {
        __syncthreads();                  // all warps done with previous buffers

        if (restage) {                    // bi changed at this tile
            const __half* Ab = g_half + (size_t)(bi * BM) * DDIM;
            #pragma unroll
            for (int i = 0; i < 8; i++) cp16(as_base + soff[i], Ab + (tid + i * 256) * 8);
            cp_commit();
        }
        if (t + 1 < end) {                // prefetch next tile's B + nB into buf^1
            int nbj = (bj + 1 < 128) ? bj + 1 : 2 * (bi + 1);
            const __half* Bb = g_half + (size_t)(nbj * BN) * DDIM;
            uint32_t nb_base = bs_base + (uint32_t)((buf ^ 1) * B_HALVES) * 2;
            #pragma unroll
            for (int i = 0; i < 4; i++) cp16(nb_base + soff[i], Bb + (tid + i * 256) * 8);
            if (tid >= BM && tid < BM + BN)
                nBb[buf ^ 1][tid - BM] = -c2l * g_sq[nbj * BN + tid - BM];
        }
        cp_commit();                      // exactly one B-group per iter (may be empty)
        if (restage && tid < BM) sqA[tid] = g_sq[bi * BM + tid];

        cp_wait1();                       // B(t) (+A if restaged) complete
        __syncthreads();

        // ---- mainloop on As, Bs[buf] ----
        uint32_t bofs = (uint32_t)(buf * B_HALVES) * 2;
        float acc[2][4][4];
        #pragma unroll
        for (int a = 0; a < 2; a++)
            #pragma unroll
            for (int b = 0; b < 4; b++)
                #pragma unroll
                for (int r = 0; r < 4; r++) acc[a][b][r] = 0.f;

        #pragma unroll
        for (int s = 0; s < 8; s++) {
            uint32_t af[2][4], bf[2][4];
            #pragma unroll
            for (int a = 0; a < 2; a++)
                ldsm4(af[a][0], af[a][1], af[a][2], af[a][3], a_addr[a] + s * 32);
            #pragma unroll
            for (int b = 0; b < 2; b++)
                ldsm4(bf[b][0], bf[b][1], bf[b][2], bf[b][3], b_addr[b] + bofs + s * 32);
            #pragma unroll
            for (int a = 0; a < 2; a++) {
                #pragma unroll
                for (int g2 = 0; g2 < 2; g2++) {
                    mma_f16(acc[a][2 * g2],     af[a], bf[g2][0], bf[g2][2]);
                    mma_f16(acc[a][2 * g2 + 1], af[a], bf[g2][1], bf[g2][3]);
                }
            }
        }

        // ---- epilogue ----
        float lsum = 0.f;
        #pragma unroll
        for (int a = 0; a < 2; a++) {
            float ea0 = c2l * sqA[m0 + 16 * a + g];
            float ea1 = c2l * sqA[m0 + 16 * a + g + 8];
            #pragma unroll
            for (int b = 0; b < 4; b++) {
                float nb0 = nBb[buf][n0 + 8 * b + t2];
                float nb1 = nBb[buf][n0 + 8 * b + t2 + 1];
                float base[4] = {nb0 - ea0, nb1 - ea0, nb0 - ea1, nb1 - ea1};
                #pragma unroll
                for (int v = 0; v < 4; v++) {
                    float x = fmaf(tc2, acc[a][b][v], base[v]);  // = -c2l*L2
                    float tt  = exp2f(x);
                    float t2v = tt * tt;
                    float u   = t2v + tt;
                    float t4  = t2v * t2v;
                    float t8  = t4 * t4;
                    float w   = fmaf(t8, t8, t8);                // t^8 + t^16
                    lsum += (u + t4) + w;
                }
            }
        }
        float si = (bi < 32) ? 1.f : -1.f;
        float sj = (bj < 64) ? 1.f : -1.f;
        float wgt = (bj >= 2 * bi + 2) ? 2.f : 1.f;   // strictly-above-diagonal tiles x2
        csum = fmaf(lsum, si * sj * wgt, csum);

        // advance tile
        buf ^= 1;
        bj++;
        restage = false;
        if (bj == 128) { bi++; bj = 2 * bi; restage = true; }
    }

    // ---- chunk reduction + finalize ----
    #pragma unroll
    for (int o = 16; o; o >>= 1) csum += __shfl_xor_sync(0xffffffffu, csum, o);
    if (lane == 0) red[wid] = csum;
    __syncthreads();
    if (tid == 0) {
        float b = 0.f;
        #pragma unroll
        for (int wi = 0; wi < 8; wi++) b += red[wi];
        atomicAdd(&g_acc, (double)b);
        __threadfence();
        if (atomicAdd(&g_done_main, 1u) == NPERS - 1) {
            out[0] = (float)(g_acc * (1.0 / ((double)NHALF * (double)NHALF)));
            g_acc = 0.0;
            g_S = 0.f;
            g_done_main = 0u;
            #pragma unroll
            for (int i = 0; i < DDIM; i++) g_v[i] = 0.f;
        }
    }
}

extern "C" void kernel_launch(void* const* d_in, const int* in_sizes, int n_in,
                              void* d_out, int out_size) {
    const float* src = (const float*)d_in[0];
    const float* tgt = (const float*)d_in[1];
    float* out = (float*)d_out;

    cudaFuncSetAttribute(k_main, cudaFuncAttributeMaxDynamicSharedMemorySize, SMEM_BYTES);

    k_rows<<<MTOT / 8, 256>>>(src, tgt);
    k_main<<<NPERS, 256, SMEM_BYTES>>>(out);
}

// round 17
// speedup vs baseline: 1.1811x; 1.1811x over previous
#include <cuda_runtime.h>
#include <cuda_fp16.h>
#include <math.h>
#include <cstdint>

#define MTOT 8192
#define NHALF 4096
#define DDIM 128
#define BM 128
#define BN 128
#define NTILES 2080             // 64*65/2 upper-triangle tiles
#define NPERS 296               // persistent CTAs: 2 per SM x 148
#define ROWBLOCKS (MTOT / 8)
#define LDH 136                 // smem row stride in halves (272B: ldmatrix conflict-free)
#define A_HALVES (DDIM * LDH)
#define B_HALVES (DDIM * LDH)
#define SMEM_BYTES ((A_HALVES + 2 * B_HALVES) * 2)   // 104448 B

__device__ __half g_half[MTOT * DDIM];   // fp16 copy of [src; tgt]
__device__ float  g_sq[MTOT];
__device__ float  g_v[DDIM];
__device__ float  g_S = 0.f;
__device__ float  g_c2l = 0.f;           // c*log2(e): t = exp(-c*L2) = exp2(-c2l*L2)
__device__ double g_acc = 0.0;
__device__ unsigned g_done_rows = 0u;
__device__ unsigned g_done_main = 0u;

// ---------------- helpers ----------------
__device__ __forceinline__ uint32_t smem_u32(const void* p) {
    uint32_t a;
    asm("{ .reg .u64 t; cvta.to.shared.u64 t, %1; cvt.u32.u64 %0, t; }" : "=r"(a) : "l"(p));
    return a;
}
__device__ __forceinline__ void cp16(uint32_t s, const void* g) {
    asm volatile("cp.async.cg.shared.global [%0], [%1], 16;" :: "r"(s), "l"(g));
}
__device__ __forceinline__ void cp_commit() {
    asm volatile("cp.async.commit_group;" ::: "memory");
}
__device__ __forceinline__ void cp_wait1() {
    asm volatile("cp.async.wait_group 1;" ::: "memory");
}
__device__ __forceinline__ void ldsm4(uint32_t& r0, uint32_t& r1, uint32_t& r2, uint32_t& r3,
                                      uint32_t addr) {
    asm volatile("ldmatrix.sync.aligned.m8n8.x4.shared.b16 {%0,%1,%2,%3}, [%4];"
                 : "=r"(r0), "=r"(r1), "=r"(r2), "=r"(r3) : "r"(addr));
}
__device__ __forceinline__ void mma_f16(float* d, const uint32_t* a,
                                        uint32_t b0, uint32_t b1) {
    asm volatile(
        "mma.sync.aligned.m16n8k16.row.col.f32.f16.f16.f32 "
        "{%0,%1,%2,%3}, {%4,%5,%6,%7}, {%8,%9}, {%0,%1,%2,%3};"
        : "+f"(d[0]), "+f"(d[1]), "+f"(d[2]), "+f"(d[3])
        : "r"(a[0]), "r"(a[1]), "r"(a[2]), "r"(a[3]), "r"(b0), "r"(b1));
}
// force the MUFU fast path (exp2f may lower to a range-reduced libcall otherwise)
__device__ __forceinline__ float ex2f(float x) {
    float r;
    asm("ex2.approx.f32 %0, %1;" : "=f"(r) : "f"(x));
    return r;
}

// ---- prep: row norms + col sums + fp16 convert; LAST block computes bandwidth ----
__global__ void k_rows(const float* __restrict__ src, const float* __restrict__ tgt) {
    __shared__ float cs[DDIM];
    __shared__ float ss;
    __shared__ unsigned s_last;
    int warp = threadIdx.x >> 5, lane = threadIdx.x & 31;
    int row = blockIdx.x * 8 + warp;
    const float* p = (row < NHALF) ? (src + (size_t)row * DDIM)
                                   : (tgt + (size_t)(row - NHALF) * DDIM);
    float4 x = ((const float4*)p)[lane];

    union { __half2 h[2]; uint2 u; } ph;
    ph.h[0] = __floats2half2_rn(x.x, x.y);
    ph.h[1] = __floats2half2_rn(x.z, x.w);
    ((uint2*)(g_half + (size_t)row * DDIM))[lane] = ph.u;

    float s = x.x*x.x + x.y*x.y + x.z*x.z + x.w*x.w;
    if (threadIdx.x < DDIM) cs[threadIdx.x] = 0.f;
    if (threadIdx.x == 0) ss = 0.f;
    __syncthreads();
    atomicAdd(&cs[lane*4+0], x.x); atomicAdd(&cs[lane*4+1], x.y);
    atomicAdd(&cs[lane*4+2], x.z); atomicAdd(&cs[lane*4+3], x.w);
    #pragma unroll
    for (int o = 16; o; o >>= 1) s += __shfl_xor_sync(0xffffffffu, s, o);
    if (lane == 0) { g_sq[row] = s; atomicAdd(&ss, s); }
    __syncthreads();
    if (threadIdx.x < DDIM) atomicAdd(&g_v[threadIdx.x], cs[threadIdx.x]);
    if (threadIdx.x == 0)   atomicAdd(&g_S, ss);

    __threadfence();
    if (threadIdx.x == 0) s_last = (atomicAdd(&g_done_rows, 1u) == ROWBLOCKS - 1);
    __syncthreads();
    if (s_last && warp == 0) {
        float vv = 0.f;
        #pragma unroll
        for (int i = 0; i < 4; i++) {
            float v = g_v[lane + 32 * i];
            vv += v * v;
        }
        #pragma unroll
        for (int o = 16; o; o >>= 1) vv += __shfl_xor_sync(0xffffffffu, vv, o);
        if (lane == 0) {
            double sumL2 = 2.0 * (double)MTOT * (double)g_S - 2.0 * (double)vv;
            double bw = sumL2 / ((double)MTOT * (double)MTOT - (double)MTOT);
            bw *= 0.25;
            double c = 1.0 / (16.0 * bw);
            g_c2l = (float)(c * 1.4426950408889634);
            g_done_rows = 0u;
        }
    }
}

// ---------------- main: persistent pipelined fp16 mma kernel ----------------
extern __shared__ __half dsmh[];

__global__ void __launch_bounds__(256, 2)
k_main(float* __restrict__ out) {
    __half* As = dsmh;                          // A panel (rows bi*128..)
    __half* Bs0 = dsmh + A_HALVES;              // B double buffer
    __shared__ float sqA[BM];
    __shared__ float nBb[2][BN];
    __shared__ float red[8];

    int tid = threadIdx.x;
    int wid = tid >> 5, lane = tid & 31;

    int c = blockIdx.x;
    int start = (int)(((long long)c * NTILES) / NPERS);
    int end   = (int)(((long long)(c + 1) * NTILES) / NPERS);

    // decode start -> (bi, bj)
    int bi = (int)((129.0 - sqrt(16641.0 - 8.0 * (double)start)) * 0.5);
    while ((bi + 1) * (129 - (bi + 1)) / 2 <= start) bi++;
    while (bi * (129 - bi) / 2 > start) bi--;
    int bj = bi + (start - bi * (129 - bi) / 2);

    float c2l = g_c2l;

    uint32_t as_base = smem_u32(As);
    uint32_t bs_base = smem_u32(Bs0);

    uint32_t soff[8];
    #pragma unroll
    for (int i = 0; i < 8; i++) {
        int idx = tid + i * 256;
        soff[i] = (uint32_t)((idx >> 4) * LDH + (idx & 15) * 8) * 2;
    }

    // ---- prologue: stage A(bi) [group], B(bj)->buf0 [group], sqA, nBb[0] ----
    {
        const __half* Ab = g_half + (size_t)(bi * BM) * DDIM;
        #pragma unroll
        for (int i = 0; i < 8; i++) cp16(as_base + soff[i], Ab + (tid + i * 256) * 8);
        cp_commit();
        const __half* Bb = g_half + (size_t)(bj * BN) * DDIM;
        #pragma unroll
        for (int i = 0; i < 8; i++) cp16(bs_base + soff[i], Bb + (tid + i * 256) * 8);
        cp_commit();
        if (tid < BM) sqA[tid] = g_sq[bi * BM + tid];
        else          nBb[0][tid - BM] = -c2l * g_sq[bj * BN + tid - BM];
    }

    // warp tiling: 2 (m) x 4 (n); warp tile 64x32
    int wm = wid & 1, wn = wid >> 1;
    int m0 = wm * 64, n0 = wn * 32;
    uint32_t a_addr[4], b_addr0[2];
    {
        int rr = lane & 15;
        int cc = 8 * (lane >> 4);
        #pragma unroll
        for (int a = 0; a < 4; a++)
            a_addr[a] = as_base + (uint32_t)((m0 + 16 * a + rr) * LDH + cc) * 2;
        #pragma unroll
        for (int b = 0; b < 2; b++)
            b_addr0[b] = bs_base + (uint32_t)((n0 + 16 * b + rr) * LDH + cc) * 2;
    }

    int g = lane >> 2, t2 = (lane & 3) * 2;
    float tc2 = 2.0f * c2l;
    float csum = 0.f;
    int buf = 0;
    bool restage = false;

    for (int t = start; t < end; t++) {
        __syncthreads();                  // all warps done with previous buffers

        if (restage) {                    // bi changed at this tile
            const __half* Ab = g_half + (size_t)(bi * BM) * DDIM;
            #pragma unroll
            for (int i = 0; i < 8; i++) cp16(as_base + soff[i], Ab + (tid + i * 256) * 8);
            cp_commit();
        }
        if (t + 1 < end) {                // prefetch next tile's B + nB into buf^1
            int nbj = bj + 1;
            if (nbj == 64) nbj = bi + 1;
            const __half* Bb = g_half + (size_t)(nbj * BN) * DDIM;
            uint32_t nb_base = bs_base + (uint32_t)((buf ^ 1) * B_HALVES) * 2;
            #pragma unroll
            for (int i = 0; i < 8; i++) cp16(nb_base + soff[i], Bb + (tid + i * 256) * 8);
            if (tid >= BM) nBb[buf ^ 1][tid - BM] = -c2l * g_sq[nbj * BN + tid - BM];
        }
        cp_commit();                      // exactly one B-group per iter (may be empty)
        if (restage && tid < BM) sqA[tid] = g_sq[bi * BM + tid];

        cp_wait1();                       // B(t) (+A if restaged) complete
        __syncthreads();

        // ---- mainloop on As, Bs[buf] ----
        uint32_t bofs = (uint32_t)(buf * B_HALVES) * 2;
        float acc[4][4][4];
        #pragma unroll
        for (int a = 0; a < 4; a++)
            #pragma unroll
            for (int b = 0; b < 4; b++)
                #pragma unroll
                for (int r = 0; r < 4; r++) acc[a][b][r] = 0.f;

        #pragma unroll
        for (int s = 0; s < 8; s++) {
            uint32_t af[4][4], bf[2][4];
            #pragma unroll
            for (int a = 0; a < 4; a++)
                ldsm4(af[a][0], af[a][1], af[a][2], af[a][3], a_addr[a] + s * 32);
            #pragma unroll
            for (int b = 0; b < 2; b++)
                ldsm4(bf[b][0], bf[b][1], bf[b][2], bf[b][3], b_addr0[b] + bofs + s * 32);
            #pragma unroll
            for (int a = 0; a < 4; a++) {
                #pragma unroll
                for (int g2 = 0; g2 < 2; g2++) {
                    mma_f16(acc[a][2 * g2],     af[a], bf[g2][0], bf[g2][2]);
                    mma_f16(acc[a][2 * g2 + 1], af[a], bf[g2][1], bf[g2][3]);
                }
            }
        }

        // ---- epilogue: fp32, forced MUFU ex2 ----
        float lsum = 0.f;
        #pragma unroll
        for (int a = 0; a < 4; a++) {
            float ea0 = c2l * sqA[m0 + 16 * a + g];
            float ea1 = c2l * sqA[m0 + 16 * a + g + 8];
            #pragma unroll
            for (int b = 0; b < 4; b++) {
                float nb0 = nBb[buf][n0 + 8 * b + t2];
                float nb1 = nBb[buf][n0 + 8 * b + t2 + 1];
                float base[4] = {nb0 - ea0, nb1 - ea0, nb0 - ea1, nb1 - ea1};
                #pragma unroll
                for (int v = 0; v < 4; v++) {
                    float x = fmaf(tc2, acc[a][b][v], base[v]);  // = -c2l*L2
                    float tt  = ex2f(x);
                    float t2v = tt * tt;
                    float u   = t2v + tt;                  // t + t^2
                    float t4  = t2v * t2v;
                    float t8  = t4 * t4;
                    float w   = fmaf(t8, t8, t8);          // t^8 + t^16
                    lsum += (u + t4) + w;
                }
            }
        }
        float si = (bi < 32) ? 1.f : -1.f;
        float sj = (bj < 32) ? 1.f : -1.f;
        csum = fmaf(lsum, si * sj * ((bi == bj) ? 1.f : 2.f), csum);

        // advance tile
        buf ^= 1;
        bj++;
        restage = false;
        if (bj == 64) { bi++; bj = bi; restage = true; }
    }

    // ---- chunk reduction + finalize ----
    #pragma unroll
    for (int o = 16; o; o >>= 1) csum += __shfl_xor_sync(0xffffffffu, csum, o);
    if (lane == 0) red[wid] = csum;
    __syncthreads();
    if (tid == 0) {
        float b = 0.f;
        #pragma unroll
        for (int wi = 0; wi < 8; wi++) b += red[wi];
        atomicAdd(&g_acc, (double)b);
        __threadfence();
        if (atomicAdd(&g_done_main, 1u) == NPERS - 1) {
            out[0] = (float)(g_acc * (1.0 / ((double)NHALF * (double)NHALF)));
            g_acc = 0.0;
            g_S = 0.f;
            g_done_main = 0u;
            #pragma unroll
            for (int i = 0; i < DDIM; i++) g_v[i] = 0.f;
        }
    }
}

extern "C" void kernel_launch(void* const* d_in, const int* in_sizes, int n_in,
                              void* d_out, int out_size) {
    const float* src = (const float*)d_in[0];
    const float* tgt = (const float*)d_in[1];
    float* out = (float*)d_out;

    cudaFuncSetAttribute(k_main, cudaFuncAttributeMaxDynamicSharedMemorySize, SMEM_BYTES);

    k_rows<<<MTOT / 8, 256>>>(src, tgt);
    k_main<<<NPERS, 256, SMEM_BYTES>>>(out);
}